// round 5
// baseline (speedup 1.0000x reference)
#include <cuda_runtime.h>
#include <math.h>

// ---------------------------------------------------------------------------
// FourierTransformLayer: out = real(ifft2( fft2(x) * W )) with
//   W[c,k1,k2] = mask[(k1+256)&511,(k2+256)&511] * param[c,(k1+256)&511,(k2+256)&511] / (512*512)
// (fftshift/ifftshift folded into the index shift; ifft2 normalization folded into W)
//
// Pipeline:
//   k_weights  : build W in bit-reversed (p1,p2) layout  -> g_wbr
//   k_row_fwd  : 512-pt DIF FFT along rows (output at bit-reversed positions) -> g_spec
//   k_col_fused: per 8-column tile: DIF col FFT -> multiply Wbr -> DIT col iFFT (all in smem)
//   k_row_inv  : DIT iFFT along rows (consumes bit-reversed positions), write real part
// ---------------------------------------------------------------------------

#define N      512
#define LOGN   9
#define HALF   256
#define NIMG   96      // 32 batch * 3 channels

__device__ float2 g_spec[(size_t)NIMG * N * N];   // ~192 MB scratch
__device__ float  g_wbr[3 * N * N];               // weights, bit-reversed layout

__device__ __forceinline__ float2 cadd(float2 a, float2 b) { return make_float2(a.x + b.x, a.y + b.y); }
__device__ __forceinline__ float2 csub(float2 a, float2 b) { return make_float2(a.x - b.x, a.y - b.y); }
__device__ __forceinline__ float2 cmul(float2 a, float2 b) {
    return make_float2(a.x * b.x - a.y * b.y, a.x * b.y + a.y * b.x);
}
// a * conj(b)
__device__ __forceinline__ float2 cmulc(float2 a, float2 b) {
    return make_float2(a.x * b.x + a.y * b.y, a.y * b.x - a.x * b.y);
}

// ---------------------------------------------------------------------------
// Weight table: Wbr[c, p1, p2] = mask(sh,sw) * param[c, sh, sw] / N^2
// where k = brev9(p), sh = (k+256)&511
// ---------------------------------------------------------------------------
__global__ void k_weights(const float* __restrict__ param) {
    int idx = blockIdx.x * blockDim.x + threadIdx.x;
    if (idx >= 3 * N * N) return;
    int c   = idx >> 18;            // / (N*N)
    int rem = idx & (N * N - 1);
    int p1  = rem >> LOGN;
    int p2  = rem & (N - 1);
    int k1  = (int)(__brev((unsigned)p1) >> (32 - LOGN));
    int k2  = (int)(__brev((unsigned)p2) >> (32 - LOGN));
    int sh  = (k1 + HALF) & (N - 1);
    int sw  = (k2 + HALF) & (N - 1);

    float dh = fabsf((float)(sh - HALF));
    float dw = fabsf((float)(sw - HALF));
    float r2 = dh * dh + dw * dw;
    float mval;
    if (r2 <= 1.0f) {
        mval = 0.5f;                               // SMOOTHNESS
    } else {
        float dist = sqrtf(r2) * (1.0f / 256.0f);  // sqrt((dh/256)^2 + (dw/256)^2)
        mval = fmaxf(1.0f, dist * 2.0f);           // dist / SMOOTHNESS
    }
    float pv = param[c * (N * N) + sh * N + sw];
    g_wbr[idx] = mval * pv * (1.0f / (float)(N * N));
}

// ---------------------------------------------------------------------------
// Row forward FFT (DIF, in-place in smem, output in bit-reversed positions).
// 4 rows per block, 128 threads per row (2 butterflies each per stage).
// ---------------------------------------------------------------------------
__global__ void __launch_bounds__(512) k_row_fwd(const float* __restrict__ x) {
    __shared__ float2 S[4 * N];
    __shared__ float2 LUT[HALF];   // LUT[k] = exp(-2*pi*i*k/512)

    int tid = threadIdx.x;
    if (tid < HALF) {
        float s, c;
        sincospif(-(float)tid * (1.0f / 256.0f), &s, &c);
        LUT[tid] = make_float2(c, s);
    }
    int r = tid >> 7;
    int l = tid & 127;
    float2* Sr = S + r * N;
    size_t row = (size_t)blockIdx.x * 4 + r;
    const float* xr = x + row * N;

    #pragma unroll
    for (int k = 0; k < 4; ++k)
        Sr[l + (k << 7)] = make_float2(xr[l + (k << 7)], 0.0f);
    __syncthreads();

    #pragma unroll
    for (int sl = LOGN - 1; sl >= 0; --sl) {
        int m = 1 << sl;
        #pragma unroll
        for (int q = 0; q < 2; ++q) {
            int t  = l + (q << 7);
            int j  = t & (m - 1);
            int i0 = ((t >> sl) << (sl + 1)) | j;
            float2 u = Sr[i0];
            float2 v = Sr[i0 + m];
            float2 w = LUT[j << (8 - sl)];
            Sr[i0]     = cadd(u, v);
            Sr[i0 + m] = cmul(csub(u, v), w);
        }
        __syncthreads();
    }

    float2* o = g_spec + row * N;
    #pragma unroll
    for (int k = 0; k < 4; ++k)
        o[l + (k << 7)] = Sr[l + (k << 7)];
}

// ---------------------------------------------------------------------------
// Fused column pass: forward DIF -> weight multiply -> inverse DIT.
// Block = 8 columns of one image, 512 threads (c = tid&7, u = tid>>3).
// Shared layout S[i*8 + c] (column-interleaved, conflict-free for bulk access).
// ---------------------------------------------------------------------------
__global__ void __launch_bounds__(512) k_col_fused() {
    __shared__ float2 S[N * 8];
    __shared__ float2 LUT[HALF];

    int tid = threadIdx.x;
    if (tid < HALF) {
        float s, c;
        sincospif(-(float)tid * (1.0f / 256.0f), &s, &c);
        LUT[tid] = make_float2(c, s);
    }
    int c    = tid & 7;
    int u    = tid >> 3;                 // 0..63
    int img  = blockIdx.x >> 6;          // 0..95
    int col0 = (blockIdx.x & 63) << 3;
    int ch   = img % 3;

    float2* base = g_spec + (size_t)img * (N * N) + col0;

    #pragma unroll
    for (int v = 0; v < 8; ++v) {
        int i = u + (v << 6);
        S[(i << 3) | c] = base[(size_t)i * N + c];
    }
    __syncthreads();

    // forward DIF along columns
    #pragma unroll
    for (int sl = LOGN - 1; sl >= 0; --sl) {
        int m = 1 << sl;
        #pragma unroll
        for (int v = 0; v < 4; ++v) {
            int t  = u + (v << 6);
            int j  = t & (m - 1);
            int i0 = ((t >> sl) << (sl + 1)) | j;
            float2 U = S[(i0 << 3) | c];
            float2 V = S[((i0 + m) << 3) | c];
            float2 w = LUT[j << (8 - sl)];
            S[(i0 << 3) | c]       = cadd(U, V);
            S[((i0 + m) << 3) | c] = cmul(csub(U, V), w);
        }
        __syncthreads();
    }

    // weight multiply (data at bit-reversed positions in both dims -> Wbr layout)
    const float* wcol = g_wbr + (size_t)ch * (N * N) + col0 + c;
    #pragma unroll
    for (int v = 0; v < 8; ++v) {
        int p1 = u + (v << 6);
        float wgt = wcol[(size_t)p1 * N];
        float2 a = S[(p1 << 3) | c];
        S[(p1 << 3) | c] = make_float2(a.x * wgt, a.y * wgt);
    }
    __syncthreads();

    // inverse DIT along columns (bit-reversed input -> natural output)
    #pragma unroll
    for (int sl = 0; sl <= LOGN - 1; ++sl) {
        int m = 1 << sl;
        #pragma unroll
        for (int v = 0; v < 4; ++v) {
            int t  = u + (v << 6);
            int j  = t & (m - 1);
            int i0 = ((t >> sl) << (sl + 1)) | j;
            float2 U = S[(i0 << 3) | c];
            float2 V = cmulc(S[((i0 + m) << 3) | c], LUT[j << (8 - sl)]);  // * conj = +angle
            S[(i0 << 3) | c]       = cadd(U, V);
            S[((i0 + m) << 3) | c] = csub(U, V);
        }
        __syncthreads();
    }

    #pragma unroll
    for (int v = 0; v < 8; ++v) {
        int i = u + (v << 6);
        base[(size_t)i * N + c] = S[(i << 3) | c];
    }
}

// ---------------------------------------------------------------------------
// Row inverse FFT (DIT; input positions are already bit-reversed from pass 1),
// write real part. Scale (1/N^2) was folded into the weights.
// ---------------------------------------------------------------------------
__global__ void __launch_bounds__(512) k_row_inv(float* __restrict__ out) {
    __shared__ float2 S[4 * N];
    __shared__ float2 LUT[HALF];

    int tid = threadIdx.x;
    if (tid < HALF) {
        float s, c;
        sincospif(-(float)tid * (1.0f / 256.0f), &s, &c);
        LUT[tid] = make_float2(c, s);
    }
    int r = tid >> 7;
    int l = tid & 127;
    float2* Sr = S + r * N;
    size_t row = (size_t)blockIdx.x * 4 + r;
    const float2* in = g_spec + row * N;

    #pragma unroll
    for (int k = 0; k < 4; ++k)
        Sr[l + (k << 7)] = in[l + (k << 7)];
    __syncthreads();

    #pragma unroll
    for (int sl = 0; sl <= LOGN - 1; ++sl) {
        int m = 1 << sl;
        #pragma unroll
        for (int q = 0; q < 2; ++q) {
            int t  = l + (q << 7);
            int j  = t & (m - 1);
            int i0 = ((t >> sl) << (sl + 1)) | j;
            float2 U = Sr[i0];
            float2 V = cmulc(Sr[i0 + m], LUT[j << (8 - sl)]);
            Sr[i0]     = cadd(U, V);
            Sr[i0 + m] = csub(U, V);
        }
        __syncthreads();
    }

    float* o = out + row * N;
    #pragma unroll
    for (int k = 0; k < 4; ++k)
        o[l + (k << 7)] = Sr[l + (k << 7)].x;
}

// ---------------------------------------------------------------------------
extern "C" void kernel_launch(void* const* d_in, const int* in_sizes, int n_in,
                              void* d_out, int out_size) {
    const float* x = (const float*)d_in[0];
    const float* p = (const float*)d_in[1];
    // x is [32,3,512,512] (25165824 elems), param is [3,512,512] (786432 elems).
    if (n_in >= 2 && in_sizes[0] < in_sizes[1]) { const float* t = x; x = p; p = t; }
    float* out = (float*)d_out;

    k_weights<<<(3 * N * N + 255) / 256, 256>>>(p);
    k_row_fwd<<<NIMG * N / 4, 512>>>(x);
    k_col_fused<<<NIMG * (N / 8), 512>>>();
    k_row_inv<<<NIMG * N / 4, 512>>>(out);
}

// round 6
// speedup vs baseline: 2.7476x; 2.7476x over previous
#include <cuda_runtime.h>
#include <math.h>

// ---------------------------------------------------------------------------
// FourierTransformLayer: out = real(ifft2( fft2(x) * W )),
//   W[c,k1,k2] = mask((k1+256)&511,(k2+256)&511) * param[c,...] / 512^2
//
// Register-resident radix-8 FFTs (512 = 8^3): 64 threads per FFT, 8 complex
// values per thread, 3 radix-8 stages, only 2 shared-memory exchanges.
// Forward = DIF (output base-8 digit-reversed), inverse = DIT (consumes
// digit-reversed input) -> no reordering anywhere; weights are baked in
// digit-reversed layout. Column pass fuses fwd FFT -> weight -> inv FFT with
// zero exchange between the multiply and the first inverse stage.
// ---------------------------------------------------------------------------

#define N      512
#define HALF   256
#define NIMG   96            // 32 batch * 3 channels
#define SMAP(p) ((p) + ((p) >> 3))   // bank-conflict skew, max 511 -> 574

__device__ float2 g_spec[(size_t)NIMG * N * N];   // ~192 MB scratch
__device__ float  g_wbr[3 * N * N];               // weights, digit-reversed layout

__device__ __forceinline__ float2 cadd(float2 a, float2 b) { return make_float2(a.x + b.x, a.y + b.y); }
__device__ __forceinline__ float2 csub(float2 a, float2 b) { return make_float2(a.x - b.x, a.y - b.y); }
__device__ __forceinline__ float2 cmul(float2 a, float2 b) {
    return make_float2(a.x * b.x - a.y * b.y, a.x * b.y + a.y * b.x);
}
// a * conj(b)
__device__ __forceinline__ float2 cmulc(float2 a, float2 b) {
    return make_float2(a.x * b.x + a.y * b.y, a.y * b.x - a.x * b.y);
}

// 8-point DFT, natural order in AND out. INV -> conjugate twiddles (unnormalized).
template<bool INV>
__device__ __forceinline__ void dft8(float2 v[8]) {
    const float s = 0.70710678118654752440f;
    float2 b0 = cadd(v[0], v[4]), t4 = csub(v[0], v[4]);
    float2 b1 = cadd(v[1], v[5]), t5 = csub(v[1], v[5]);
    float2 b2 = cadd(v[2], v[6]), t6 = csub(v[2], v[6]);
    float2 b3 = cadd(v[3], v[7]), t7 = csub(v[3], v[7]);
    float2 b4 = t4;
    float2 b5 = INV ? make_float2(s * (t5.x - t5.y), s * (t5.x + t5.y))    // *( s, s)
                    : make_float2(s * (t5.x + t5.y), s * (t5.y - t5.x));   // *( s,-s)
    float2 b6 = INV ? make_float2(-t6.y, t6.x)                             // *(+i)
                    : make_float2(t6.y, -t6.x);                            // *(-i)
    float2 b7 = INV ? make_float2(-s * (t7.x + t7.y), s * (t7.x - t7.y))   // *(-s, s)
                    : make_float2(s * (t7.y - t7.x), -s * (t7.x + t7.y));  // *(-s,-s)
    float2 c0 = cadd(b0, b2), u2 = csub(b0, b2);
    float2 c1 = cadd(b1, b3), u3 = csub(b1, b3);
    float2 c4 = cadd(b4, b6), u6 = csub(b4, b6);
    float2 c5 = cadd(b5, b7), u7 = csub(b5, b7);
    float2 c2 = u2;
    float2 c3 = INV ? make_float2(-u3.y, u3.x) : make_float2(u3.y, -u3.x);
    float2 c6 = u6;
    float2 c7 = INV ? make_float2(-u7.y, u7.x) : make_float2(u7.y, -u7.x);
    v[0] = cadd(c0, c1); v[4] = csub(c0, c1);
    v[2] = cadd(c2, c3); v[6] = csub(c2, c3);
    v[1] = cadd(c4, c5); v[5] = csub(c4, c5);
    v[3] = cadd(c6, c7); v[7] = csub(c6, c7);
}

// After forward DFT8: v[r] *= w1^r  (w1 = W_{8m}^j, negative-angle)
__device__ __forceinline__ void twiddle_out(float2 v[8], float2 w1) {
    float2 w2 = cmul(w1, w1);
    float2 w3 = cmul(w2, w1);
    float2 w4 = cmul(w2, w2);
    float2 w5 = cmul(w3, w2);
    float2 w6 = cmul(w3, w3);
    float2 w7 = cmul(w4, w3);
    v[1] = cmul(v[1], w1); v[2] = cmul(v[2], w2); v[3] = cmul(v[3], w3);
    v[4] = cmul(v[4], w4); v[5] = cmul(v[5], w5); v[6] = cmul(v[6], w6);
    v[7] = cmul(v[7], w7);
}

// Before inverse DFT8: v[q] *= conj(w1^q)
__device__ __forceinline__ void twiddle_in_conj(float2 v[8], float2 w1) {
    float2 w2 = cmul(w1, w1);
    float2 w3 = cmul(w2, w1);
    float2 w4 = cmul(w2, w2);
    float2 w5 = cmul(w3, w2);
    float2 w6 = cmul(w3, w3);
    float2 w7 = cmul(w4, w3);
    v[1] = cmulc(v[1], w1); v[2] = cmulc(v[2], w2); v[3] = cmulc(v[3], w3);
    v[4] = cmulc(v[4], w4); v[5] = cmulc(v[5], w5); v[6] = cmulc(v[6], w6);
    v[7] = cmulc(v[7], w7);
}

__device__ __forceinline__ void init_lut(float2* LUT, int tid) {
    float s, c;
    sincospif(-(float)tid * (1.0f / 256.0f), &s, &c);
    LUT[tid] = make_float2(c, s);   // LUT[k] = exp(-2*pi*i*k/512)
}

// ---------------------------------------------------------------------------
// Weight table in base-8 digit-reversed layout (both dims).
// ---------------------------------------------------------------------------
__device__ __forceinline__ int octrev9(int p) {
    return ((p & 7) << 6) | (p & 56) | ((p >> 6) & 7);
}

__global__ void k_weights(const float* __restrict__ param) {
    int idx = blockIdx.x * blockDim.x + threadIdx.x;
    if (idx >= 3 * N * N) return;
    int c   = idx >> 18;
    int rem = idx & (N * N - 1);
    int k1  = octrev9(rem >> 9);
    int k2  = octrev9(rem & (N - 1));
    int sh  = (k1 + HALF) & (N - 1);
    int sw  = (k2 + HALF) & (N - 1);

    float dh = fabsf((float)(sh - HALF));
    float dw = fabsf((float)(sw - HALF));
    float r2 = dh * dh + dw * dw;
    float mval;
    if (r2 <= 1.0f) {
        mval = 0.5f;                               // SMOOTHNESS
    } else {
        float dist = sqrtf(r2) * (1.0f / 256.0f);
        mval = fmaxf(1.0f, dist * 2.0f);           // dist / SMOOTHNESS
    }
    float pv = param[c * (N * N) + sh * N + sw];
    g_wbr[idx] = mval * pv * (1.0f / (float)(N * N));
}

// ---------------------------------------------------------------------------
// Row forward FFT (radix-8 DIF). 8 rows/block, 64 threads/row.
// Output digit-reversed, stored as contiguous float4s.
// ---------------------------------------------------------------------------
__global__ void __launch_bounds__(512) k_row_fwd(const float* __restrict__ x) {
    __shared__ float2 LUT[N];
    __shared__ float2 S[8 * 576];

    int tid = threadIdx.x;
    init_lut(LUT, tid);
    int rl = tid >> 6;
    int t  = tid & 63;
    float2* Sr = S + rl * 576;
    size_t row = (size_t)blockIdx.x * 8 + rl;
    const float* xr = x + row * N;

    float2 v[8];
    #pragma unroll
    for (int q = 0; q < 8; ++q) v[q] = make_float2(xr[t + (q << 6)], 0.0f);
    __syncthreads();   // LUT ready

    // stage m=64 (j = t)
    dft8<false>(v);
    twiddle_out(v, LUT[t]);
    #pragma unroll
    for (int r = 0; r < 8; ++r) { int p = t + (r << 6); Sr[SMAP(p)] = v[r]; }
    __syncthreads();
    #pragma unroll
    for (int q = 0; q < 8; ++q) { int p = ((t >> 3) << 6) + (t & 7) + (q << 3); v[q] = Sr[SMAP(p)]; }
    __syncthreads();

    // stage m=8 (j = t&7)
    dft8<false>(v);
    twiddle_out(v, LUT[(t & 7) << 3]);
    #pragma unroll
    for (int r = 0; r < 8; ++r) { int p = ((t >> 3) << 6) + (t & 7) + (r << 3); Sr[SMAP(p)] = v[r]; }
    __syncthreads();
    #pragma unroll
    for (int q = 0; q < 8; ++q) { int p = (t << 3) + q; v[q] = Sr[SMAP(p)]; }

    // stage m=1
    dft8<false>(v);

    // positions 8t..8t+7 contiguous -> 4x float4
    float4* o = (float4*)(g_spec + row * N + (t << 3));
    o[0] = make_float4(v[0].x, v[0].y, v[1].x, v[1].y);
    o[1] = make_float4(v[2].x, v[2].y, v[3].x, v[3].y);
    o[2] = make_float4(v[4].x, v[4].y, v[5].x, v[5].y);
    o[3] = make_float4(v[6].x, v[6].y, v[7].x, v[7].y);
}

// ---------------------------------------------------------------------------
// Fused column pass: fwd radix-8 DIF -> weight multiply -> inv radix-8 DIT.
// Block = 8 columns of one image; c = tid&7, u = tid>>3 (64-thread FFT).
// The multiply happens in registers: fwd output positions == inv m=1 inputs.
// ---------------------------------------------------------------------------
__global__ void __launch_bounds__(512) k_col_fused() {
    __shared__ float2 LUT[N];
    __shared__ float2 S[575 * 8];

    int tid  = threadIdx.x;
    init_lut(LUT, tid);
    int c    = tid & 7;
    int u    = tid >> 3;
    int img  = blockIdx.x >> 6;
    int col0 = (blockIdx.x & 63) << 3;
    int ch   = img % 3;

    float2* base = g_spec + (size_t)img * (N * N) + col0 + c;
    int h64 = (u >> 3) << 6;
    int j8  = u & 7;

    float2 v[8];
    #pragma unroll
    for (int q = 0; q < 8; ++q) v[q] = base[(size_t)(u + (q << 6)) * N];
    __syncthreads();   // LUT ready

    // ---- forward: stage m=64 (j = u) ----
    dft8<false>(v);
    twiddle_out(v, LUT[u]);
    #pragma unroll
    for (int r = 0; r < 8; ++r) { int p = u + (r << 6); S[(SMAP(p) << 3) | c] = v[r]; }
    __syncthreads();
    #pragma unroll
    for (int q = 0; q < 8; ++q) { int p = h64 + j8 + (q << 3); v[q] = S[(SMAP(p) << 3) | c]; }
    __syncthreads();

    // ---- forward: stage m=8 (j = u&7) ----
    dft8<false>(v);
    twiddle_out(v, LUT[j8 << 3]);
    #pragma unroll
    for (int r = 0; r < 8; ++r) { int p = h64 + j8 + (r << 3); S[(SMAP(p) << 3) | c] = v[r]; }
    __syncthreads();
    #pragma unroll
    for (int q = 0; q < 8; ++q) { int p = (u << 3) + q; v[q] = S[(SMAP(p) << 3) | c]; }

    // ---- forward: stage m=1 ----
    dft8<false>(v);

    // ---- weight multiply (digit-reversed in both dims) ----
    const float* wp = g_wbr + (size_t)ch * (N * N) + (size_t)(u << 3) * N + col0 + c;
    #pragma unroll
    for (int r = 0; r < 8; ++r) {
        float w = wp[(size_t)r * N];
        v[r].x *= w; v[r].y *= w;
    }

    // ---- inverse: stage m=1 (registers already hold positions 8u+q) ----
    dft8<true>(v);
    __syncthreads();
    #pragma unroll
    for (int r = 0; r < 8; ++r) { int p = (u << 3) + r; S[(SMAP(p) << 3) | c] = v[r]; }
    __syncthreads();
    #pragma unroll
    for (int q = 0; q < 8; ++q) { int p = h64 + j8 + (q << 3); v[q] = S[(SMAP(p) << 3) | c]; }
    __syncthreads();

    // ---- inverse: stage m=8 ----
    twiddle_in_conj(v, LUT[j8 << 3]);
    dft8<true>(v);
    #pragma unroll
    for (int r = 0; r < 8; ++r) { int p = h64 + j8 + (r << 3); S[(SMAP(p) << 3) | c] = v[r]; }
    __syncthreads();
    #pragma unroll
    for (int q = 0; q < 8; ++q) { int p = u + (q << 6); v[q] = S[(SMAP(p) << 3) | c]; }

    // ---- inverse: stage m=64 ----
    twiddle_in_conj(v, LUT[u]);
    dft8<true>(v);
    #pragma unroll
    for (int r = 0; r < 8; ++r) base[(size_t)(u + (r << 6)) * N] = v[r];
}

// ---------------------------------------------------------------------------
// Row inverse FFT (radix-8 DIT, digit-reversed input -> natural). Real output.
// ---------------------------------------------------------------------------
__global__ void __launch_bounds__(512) k_row_inv(float* __restrict__ out) {
    __shared__ float2 LUT[N];
    __shared__ float2 S[8 * 576];

    int tid = threadIdx.x;
    init_lut(LUT, tid);
    int rl = tid >> 6;
    int t  = tid & 63;
    float2* Sr = S + rl * 576;
    size_t row = (size_t)blockIdx.x * 8 + rl;
    int h64 = (t >> 3) << 6;
    int j8  = t & 7;

    // contiguous float4 loads of positions 8t..8t+7
    const float4* in4 = (const float4*)(g_spec + row * N + (t << 3));
    float2 v[8];
    {
        float4 a0 = in4[0], a1 = in4[1], a2 = in4[2], a3 = in4[3];
        v[0] = make_float2(a0.x, a0.y); v[1] = make_float2(a0.z, a0.w);
        v[2] = make_float2(a1.x, a1.y); v[3] = make_float2(a1.z, a1.w);
        v[4] = make_float2(a2.x, a2.y); v[5] = make_float2(a2.z, a2.w);
        v[6] = make_float2(a3.x, a3.y); v[7] = make_float2(a3.z, a3.w);
    }

    // stage m=1
    dft8<true>(v);
    #pragma unroll
    for (int r = 0; r < 8; ++r) { int p = (t << 3) + r; Sr[SMAP(p)] = v[r]; }
    __syncthreads();   // also covers LUT init
    #pragma unroll
    for (int q = 0; q < 8; ++q) { int p = h64 + j8 + (q << 3); v[q] = Sr[SMAP(p)]; }
    __syncthreads();

    // stage m=8
    twiddle_in_conj(v, LUT[j8 << 3]);
    dft8<true>(v);
    #pragma unroll
    for (int r = 0; r < 8; ++r) { int p = h64 + j8 + (r << 3); Sr[SMAP(p)] = v[r]; }
    __syncthreads();
    #pragma unroll
    for (int q = 0; q < 8; ++q) { int p = t + (q << 6); v[q] = Sr[SMAP(p)]; }

    // stage m=64
    twiddle_in_conj(v, LUT[t]);
    dft8<true>(v);

    float* o = out + row * N;
    #pragma unroll
    for (int r = 0; r < 8; ++r) o[t + (r << 6)] = v[r].x;
}

// ---------------------------------------------------------------------------
extern "C" void kernel_launch(void* const* d_in, const int* in_sizes, int n_in,
                              void* d_out, int out_size) {
    const float* x = (const float*)d_in[0];
    const float* p = (const float*)d_in[1];
    if (n_in >= 2 && in_sizes[0] < in_sizes[1]) { const float* t = x; x = p; p = t; }
    float* out = (float*)d_out;

    k_weights<<<(3 * N * N + 255) / 256, 256>>>(p);
    k_row_fwd<<<NIMG * N / 8, 512>>>(x);
    k_col_fused<<<NIMG * (N / 8), 512>>>();
    k_row_inv<<<NIMG * N / 8, 512>>>(out);
}

// round 7
// speedup vs baseline: 4.5700x; 1.6633x over previous
#include <cuda_runtime.h>
#include <math.h>

// ---------------------------------------------------------------------------
// FourierTransformLayer: out = real(ifft2( fft2(x) * W )),
//   W[c,k1,k2] = mask((k1+256)&511,(k2+256)&511) * param[c,...] / 512^2
//
// Real-input packing: two same-channel images a,b are packed z = a + i*b.
// W is real (and conjugate-symmetric for these inputs), so
//   ifft2(W * fft2(z)) = ifft2(W*a_hat) + i*ifft2(W*b_hat)
// and out_a = Re, out_b = Im. 48 complex FFT planes instead of 96.
//
// Register-resident radix-8 FFTs (512 = 8^3): 64 threads per FFT, 8 complex
// values per thread, 3 radix-8 stages, only 2 shared-memory exchanges.
// Forward DIF leaves base-8 digit-reversed order; weights baked in that
// layout; inverse DIT consumes it. Zero reordering passes anywhere.
// ---------------------------------------------------------------------------

#define N      512
#define HALF   256
#define NPK    48            // 48 packed planes (96 real planes / 2)
#define PLANE  (N * N)
#define SMAP(p) ((p) + ((p) >> 3))   // bank-conflict skew

__device__ float2 g_spec[(size_t)NPK * PLANE];    // ~96 MB scratch
__device__ float  g_wbr[3 * PLANE];               // weights, digit-reversed layout

__device__ __forceinline__ float2 cadd(float2 a, float2 b) { return make_float2(a.x + b.x, a.y + b.y); }
__device__ __forceinline__ float2 csub(float2 a, float2 b) { return make_float2(a.x - b.x, a.y - b.y); }
__device__ __forceinline__ float2 cmul(float2 a, float2 b) {
    return make_float2(a.x * b.x - a.y * b.y, a.x * b.y + a.y * b.x);
}
// a * conj(b)
__device__ __forceinline__ float2 cmulc(float2 a, float2 b) {
    return make_float2(a.x * b.x + a.y * b.y, a.y * b.x - a.x * b.y);
}

// 8-point DFT, natural order in AND out. INV -> conjugate twiddles (unnormalized).
template<bool INV>
__device__ __forceinline__ void dft8(float2 v[8]) {
    const float s = 0.70710678118654752440f;
    float2 b0 = cadd(v[0], v[4]), t4 = csub(v[0], v[4]);
    float2 b1 = cadd(v[1], v[5]), t5 = csub(v[1], v[5]);
    float2 b2 = cadd(v[2], v[6]), t6 = csub(v[2], v[6]);
    float2 b3 = cadd(v[3], v[7]), t7 = csub(v[3], v[7]);
    float2 b4 = t4;
    float2 b5 = INV ? make_float2(s * (t5.x - t5.y), s * (t5.x + t5.y))
                    : make_float2(s * (t5.x + t5.y), s * (t5.y - t5.x));
    float2 b6 = INV ? make_float2(-t6.y, t6.x)
                    : make_float2(t6.y, -t6.x);
    float2 b7 = INV ? make_float2(-s * (t7.x + t7.y), s * (t7.x - t7.y))
                    : make_float2(s * (t7.y - t7.x), -s * (t7.x + t7.y));
    float2 c0 = cadd(b0, b2), u2 = csub(b0, b2);
    float2 c1 = cadd(b1, b3), u3 = csub(b1, b3);
    float2 c4 = cadd(b4, b6), u6 = csub(b4, b6);
    float2 c5 = cadd(b5, b7), u7 = csub(b5, b7);
    float2 c2 = u2;
    float2 c3 = INV ? make_float2(-u3.y, u3.x) : make_float2(u3.y, -u3.x);
    float2 c6 = u6;
    float2 c7 = INV ? make_float2(-u7.y, u7.x) : make_float2(u7.y, -u7.x);
    v[0] = cadd(c0, c1); v[4] = csub(c0, c1);
    v[2] = cadd(c2, c3); v[6] = csub(c2, c3);
    v[1] = cadd(c4, c5); v[5] = csub(c4, c5);
    v[3] = cadd(c6, c7); v[7] = csub(c6, c7);
}

// After forward DFT8: v[r] *= w1^r  (w1 = negative-angle root)
__device__ __forceinline__ void twiddle_out(float2 v[8], float2 w1) {
    float2 w2 = cmul(w1, w1);
    float2 w3 = cmul(w2, w1);
    float2 w4 = cmul(w2, w2);
    float2 w5 = cmul(w3, w2);
    float2 w6 = cmul(w3, w3);
    float2 w7 = cmul(w4, w3);
    v[1] = cmul(v[1], w1); v[2] = cmul(v[2], w2); v[3] = cmul(v[3], w3);
    v[4] = cmul(v[4], w4); v[5] = cmul(v[5], w5); v[6] = cmul(v[6], w6);
    v[7] = cmul(v[7], w7);
}

// Before inverse DFT8: v[q] *= conj(w1^q)
__device__ __forceinline__ void twiddle_in_conj(float2 v[8], float2 w1) {
    float2 w2 = cmul(w1, w1);
    float2 w3 = cmul(w2, w1);
    float2 w4 = cmul(w2, w2);
    float2 w5 = cmul(w3, w2);
    float2 w6 = cmul(w3, w3);
    float2 w7 = cmul(w4, w3);
    v[1] = cmulc(v[1], w1); v[2] = cmulc(v[2], w2); v[3] = cmulc(v[3], w3);
    v[4] = cmulc(v[4], w4); v[5] = cmulc(v[5], w5); v[6] = cmulc(v[6], w6);
    v[7] = cmulc(v[7], w7);
}

__device__ __forceinline__ void init_lut(float2* LUT, int tid) {
    float s, c;
    sincospif(-(float)tid * (1.0f / 256.0f), &s, &c);
    LUT[tid] = make_float2(c, s);   // LUT[k] = exp(-2*pi*i*k/512)
}

// ---------------------------------------------------------------------------
// Weight table in base-8 digit-reversed layout (both dims).
// ---------------------------------------------------------------------------
__device__ __forceinline__ int octrev9(int p) {
    return ((p & 7) << 6) | (p & 56) | ((p >> 6) & 7);
}

__global__ void k_weights(const float* __restrict__ param) {
    int idx = blockIdx.x * blockDim.x + threadIdx.x;
    if (idx >= 3 * PLANE) return;
    int c   = idx >> 18;
    int rem = idx & (PLANE - 1);
    int k1  = octrev9(rem >> 9);
    int k2  = octrev9(rem & (N - 1));
    int sh  = (k1 + HALF) & (N - 1);
    int sw  = (k2 + HALF) & (N - 1);

    float dh = fabsf((float)(sh - HALF));
    float dw = fabsf((float)(sw - HALF));
    float r2 = dh * dh + dw * dw;
    float mval;
    if (r2 <= 1.0f) {
        mval = 0.5f;                               // SMOOTHNESS
    } else {
        float dist = sqrtf(r2) * (1.0f / 256.0f);
        mval = fmaxf(1.0f, dist * 2.0f);           // dist / SMOOTHNESS
    }
    float pv = param[c * PLANE + sh * N + sw];
    g_wbr[idx] = mval * pv * (1.0f / (float)PLANE);
}

// ---------------------------------------------------------------------------
// Row forward FFT (radix-8 DIF) on packed planes z = a + i*b.
// 8 rows/block, 64 threads/row. Output digit-reversed, contiguous float4s.
// Packed plane pi -> real plane 6*(pi/3) + (pi%3), imag plane = real + 3.
// ---------------------------------------------------------------------------
__global__ void __launch_bounds__(512) k_row_fwd(const float* __restrict__ x) {
    __shared__ float2 LUT[N];
    __shared__ float2 S[8 * 576];

    int tid = threadIdx.x;
    init_lut(LUT, tid);
    int rl = tid >> 6;
    int t  = tid & 63;
    float2* Sr = S + rl * 576;

    int prow = blockIdx.x * 8 + rl;      // 0 .. NPK*512-1
    int pi   = prow >> 9;
    int r    = prow & (N - 1);
    int bp   = pi / 3;
    int ch   = pi - 3 * bp;
    const float* xre = x + (size_t)(6 * bp + ch) * PLANE + (size_t)r * N;
    const float* xim = xre + (size_t)3 * PLANE;

    float2 v[8];
    #pragma unroll
    for (int q = 0; q < 8; ++q) {
        int p = t + (q << 6);
        v[q] = make_float2(xre[p], xim[p]);
    }
    __syncthreads();   // LUT ready

    // stage m=64 (j = t)
    dft8<false>(v);
    twiddle_out(v, LUT[t]);
    #pragma unroll
    for (int r8 = 0; r8 < 8; ++r8) { int p = t + (r8 << 6); Sr[SMAP(p)] = v[r8]; }
    __syncthreads();
    #pragma unroll
    for (int q = 0; q < 8; ++q) { int p = ((t >> 3) << 6) + (t & 7) + (q << 3); v[q] = Sr[SMAP(p)]; }
    __syncthreads();

    // stage m=8 (j = t&7)
    dft8<false>(v);
    twiddle_out(v, LUT[(t & 7) << 3]);
    #pragma unroll
    for (int r8 = 0; r8 < 8; ++r8) { int p = ((t >> 3) << 6) + (t & 7) + (r8 << 3); Sr[SMAP(p)] = v[r8]; }
    __syncthreads();
    #pragma unroll
    for (int q = 0; q < 8; ++q) { int p = (t << 3) + q; v[q] = Sr[SMAP(p)]; }

    // stage m=1
    dft8<false>(v);

    float4* o = (float4*)(g_spec + (size_t)prow * N + (t << 3));
    o[0] = make_float4(v[0].x, v[0].y, v[1].x, v[1].y);
    o[1] = make_float4(v[2].x, v[2].y, v[3].x, v[3].y);
    o[2] = make_float4(v[4].x, v[4].y, v[5].x, v[5].y);
    o[3] = make_float4(v[6].x, v[6].y, v[7].x, v[7].y);
}

// ---------------------------------------------------------------------------
// Fused column pass: fwd radix-8 DIF -> real weight multiply -> inv radix-8 DIT.
// Block = 8 columns of one packed plane; c = tid&7, u = tid>>3.
// ---------------------------------------------------------------------------
__global__ void __launch_bounds__(512) k_col_fused() {
    __shared__ float2 LUT[N];
    __shared__ float2 S[575 * 8];

    int tid  = threadIdx.x;
    init_lut(LUT, tid);
    int c    = tid & 7;
    int u    = tid >> 3;
    int img  = blockIdx.x >> 6;          // 0..47
    int col0 = (blockIdx.x & 63) << 3;
    int ch   = img % 3;

    float2* base = g_spec + (size_t)img * PLANE + col0 + c;
    int h64 = (u >> 3) << 6;
    int j8  = u & 7;

    float2 v[8];
    #pragma unroll
    for (int q = 0; q < 8; ++q) v[q] = base[(size_t)(u + (q << 6)) * N];
    __syncthreads();   // LUT ready

    // ---- forward: stage m=64 ----
    dft8<false>(v);
    twiddle_out(v, LUT[u]);
    #pragma unroll
    for (int r = 0; r < 8; ++r) { int p = u + (r << 6); S[(SMAP(p) << 3) | c] = v[r]; }
    __syncthreads();
    #pragma unroll
    for (int q = 0; q < 8; ++q) { int p = h64 + j8 + (q << 3); v[q] = S[(SMAP(p) << 3) | c]; }
    __syncthreads();

    // ---- forward: stage m=8 ----
    dft8<false>(v);
    twiddle_out(v, LUT[j8 << 3]);
    #pragma unroll
    for (int r = 0; r < 8; ++r) { int p = h64 + j8 + (r << 3); S[(SMAP(p) << 3) | c] = v[r]; }
    __syncthreads();
    #pragma unroll
    for (int q = 0; q < 8; ++q) { int p = (u << 3) + q; v[q] = S[(SMAP(p) << 3) | c]; }

    // ---- forward: stage m=1 ----
    dft8<false>(v);

    // ---- weight multiply (real W; digit-reversed in both dims) ----
    const float* wp = g_wbr + (size_t)ch * PLANE + (size_t)(u << 3) * N + col0 + c;
    #pragma unroll
    for (int r = 0; r < 8; ++r) {
        float w = wp[(size_t)r * N];
        v[r].x *= w; v[r].y *= w;
    }

    // ---- inverse: stage m=1 (registers already hold positions 8u+q) ----
    dft8<true>(v);
    __syncthreads();
    #pragma unroll
    for (int r = 0; r < 8; ++r) { int p = (u << 3) + r; S[(SMAP(p) << 3) | c] = v[r]; }
    __syncthreads();
    #pragma unroll
    for (int q = 0; q < 8; ++q) { int p = h64 + j8 + (q << 3); v[q] = S[(SMAP(p) << 3) | c]; }
    __syncthreads();

    // ---- inverse: stage m=8 ----
    twiddle_in_conj(v, LUT[j8 << 3]);
    dft8<true>(v);
    #pragma unroll
    for (int r = 0; r < 8; ++r) { int p = h64 + j8 + (r << 3); S[(SMAP(p) << 3) | c] = v[r]; }
    __syncthreads();
    #pragma unroll
    for (int q = 0; q < 8; ++q) { int p = u + (q << 6); v[q] = S[(SMAP(p) << 3) | c]; }

    // ---- inverse: stage m=64 ----
    twiddle_in_conj(v, LUT[u]);
    dft8<true>(v);
    #pragma unroll
    for (int r = 0; r < 8; ++r) base[(size_t)(u + (r << 6)) * N] = v[r];
}

// ---------------------------------------------------------------------------
// Row inverse FFT (radix-8 DIT, digit-reversed input -> natural).
// Unpack: out_a = Re, out_b = Im, two coalesced real stores.
// ---------------------------------------------------------------------------
__global__ void __launch_bounds__(512) k_row_inv(float* __restrict__ out) {
    __shared__ float2 LUT[N];
    __shared__ float2 S[8 * 576];

    int tid = threadIdx.x;
    init_lut(LUT, tid);
    int rl = tid >> 6;
    int t  = tid & 63;
    float2* Sr = S + rl * 576;

    int prow = blockIdx.x * 8 + rl;
    int pi   = prow >> 9;
    int r    = prow & (N - 1);
    int bp   = pi / 3;
    int ch   = pi - 3 * bp;
    int h64  = (t >> 3) << 6;
    int j8   = t & 7;

    const float4* in4 = (const float4*)(g_spec + (size_t)prow * N + (t << 3));
    float2 v[8];
    {
        float4 a0 = in4[0], a1 = in4[1], a2 = in4[2], a3 = in4[3];
        v[0] = make_float2(a0.x, a0.y); v[1] = make_float2(a0.z, a0.w);
        v[2] = make_float2(a1.x, a1.y); v[3] = make_float2(a1.z, a1.w);
        v[4] = make_float2(a2.x, a2.y); v[5] = make_float2(a2.z, a2.w);
        v[6] = make_float2(a3.x, a3.y); v[7] = make_float2(a3.z, a3.w);
    }

    // stage m=1
    dft8<true>(v);
    #pragma unroll
    for (int r8 = 0; r8 < 8; ++r8) { int p = (t << 3) + r8; Sr[SMAP(p)] = v[r8]; }
    __syncthreads();   // also covers LUT init
    #pragma unroll
    for (int q = 0; q < 8; ++q) { int p = h64 + j8 + (q << 3); v[q] = Sr[SMAP(p)]; }
    __syncthreads();

    // stage m=8
    twiddle_in_conj(v, LUT[j8 << 3]);
    dft8<true>(v);
    #pragma unroll
    for (int r8 = 0; r8 < 8; ++r8) { int p = h64 + j8 + (r8 << 3); Sr[SMAP(p)] = v[r8]; }
    __syncthreads();
    #pragma unroll
    for (int q = 0; q < 8; ++q) { int p = t + (q << 6); v[q] = Sr[SMAP(p)]; }

    // stage m=64
    twiddle_in_conj(v, LUT[t]);
    dft8<true>(v);

    float* ore = out + (size_t)(6 * bp + ch) * PLANE + (size_t)r * N;
    float* oim = ore + (size_t)3 * PLANE;
    #pragma unroll
    for (int r8 = 0; r8 < 8; ++r8) {
        int p = t + (r8 << 6);
        ore[p] = v[r8].x;
        oim[p] = v[r8].y;
    }
}

// ---------------------------------------------------------------------------
extern "C" void kernel_launch(void* const* d_in, const int* in_sizes, int n_in,
                              void* d_out, int out_size) {
    const float* x = (const float*)d_in[0];
    const float* p = (const float*)d_in[1];
    if (n_in >= 2 && in_sizes[0] < in_sizes[1]) { const float* t = x; x = p; p = t; }
    float* out = (float*)d_out;

    k_weights<<<(3 * PLANE + 255) / 256, 256>>>(p);
    k_row_fwd<<<NPK * N / 8, 512>>>(x);
    k_col_fused<<<NPK * (N / 8), 512>>>();
    k_row_inv<<<NPK * N / 8, 512>>>(out);
}

// round 9
// speedup vs baseline: 5.8358x; 1.2770x over previous
#include <cuda_runtime.h>
#include <cuda_fp16.h>
#include <math.h>

// ---------------------------------------------------------------------------
// FourierTransformLayer: out = real(ifft2( fft2(x) * W )),
//   W[c,k1,k2] = mask((k1+256)&511,(k2+256)&511) * param[c,...] / 512^2
//
// Real-input packing: two same-channel images a,b packed z = a + i*b (W real
// and conjugate-symmetric -> out_a = Re, out_b = Im). 48 complex planes.
//
// Register-resident radix-8 FFTs (512 = 8^3): 64 threads/FFT, 8 complex per
// thread, 2 smem exchanges. Forward DIF leaves base-8 digit-reversed order,
// weights baked in that layout, inverse DIT consumes it.
//
// NEW (R8): intermediate spectrum stored as half2 (fp32 math throughout,
// quantize only at the two scratch hops) -> scratch traffic halved and the
// 48 MB spectrum fits in L2. Row kernels use 256-thread blocks for occupancy.
// ---------------------------------------------------------------------------

#define N      512
#define HALF   256
#define NPK    48            // packed planes (96 real planes / 2)
#define PLANE  (N * N)
#define SMAP(p) ((p) + ((p) >> 3))   // bank-conflict skew

__device__ unsigned g_spec[(size_t)NPK * PLANE];  // half2 per element, 48 MB
__device__ float    g_wbr[3 * PLANE];             // weights, digit-reversed layout

__device__ __forceinline__ unsigned pack_h2(float2 a) {
    __half2 h = __floats2half2_rn(a.x, a.y);
    return *reinterpret_cast<unsigned*>(&h);
}
__device__ __forceinline__ float2 unpack_h2(unsigned u) {
    __half2 h = *reinterpret_cast<__half2*>(&u);
    return __half22float2(h);
}

__device__ __forceinline__ float2 cadd(float2 a, float2 b) { return make_float2(a.x + b.x, a.y + b.y); }
__device__ __forceinline__ float2 csub(float2 a, float2 b) { return make_float2(a.x - b.x, a.y - b.y); }
__device__ __forceinline__ float2 cmul(float2 a, float2 b) {
    return make_float2(a.x * b.x - a.y * b.y, a.x * b.y + a.y * b.x);
}
// a * conj(b)
__device__ __forceinline__ float2 cmulc(float2 a, float2 b) {
    return make_float2(a.x * b.x + a.y * b.y, a.y * b.x - a.x * b.y);
}

// 8-point DFT, natural order in AND out. INV -> conjugate twiddles (unnormalized).
template<bool INV>
__device__ __forceinline__ void dft8(float2 v[8]) {
    const float s = 0.70710678118654752440f;
    float2 b0 = cadd(v[0], v[4]), t4 = csub(v[0], v[4]);
    float2 b1 = cadd(v[1], v[5]), t5 = csub(v[1], v[5]);
    float2 b2 = cadd(v[2], v[6]), t6 = csub(v[2], v[6]);
    float2 b3 = cadd(v[3], v[7]), t7 = csub(v[3], v[7]);
    float2 b4 = t4;
    float2 b5 = INV ? make_float2(s * (t5.x - t5.y), s * (t5.x + t5.y))
                    : make_float2(s * (t5.x + t5.y), s * (t5.y - t5.x));
    float2 b6 = INV ? make_float2(-t6.y, t6.x)
                    : make_float2(t6.y, -t6.x);
    float2 b7 = INV ? make_float2(-s * (t7.x + t7.y), s * (t7.x - t7.y))
                    : make_float2(s * (t7.y - t7.x), -s * (t7.x + t7.y));
    float2 c0 = cadd(b0, b2), u2 = csub(b0, b2);
    float2 c1 = cadd(b1, b3), u3 = csub(b1, b3);
    float2 c4 = cadd(b4, b6), u6 = csub(b4, b6);
    float2 c5 = cadd(b5, b7), u7 = csub(b5, b7);
    float2 c2 = u2;
    float2 c3 = INV ? make_float2(-u3.y, u3.x) : make_float2(u3.y, -u3.x);
    float2 c6 = u6;
    float2 c7 = INV ? make_float2(-u7.y, u7.x) : make_float2(u7.y, -u7.x);
    v[0] = cadd(c0, c1); v[4] = csub(c0, c1);
    v[2] = cadd(c2, c3); v[6] = csub(c2, c3);
    v[1] = cadd(c4, c5); v[5] = csub(c4, c5);
    v[3] = cadd(c6, c7); v[7] = csub(c6, c7);
}

__device__ __forceinline__ void twiddle_out(float2 v[8], float2 w1) {
    float2 w2 = cmul(w1, w1);
    float2 w3 = cmul(w2, w1);
    float2 w4 = cmul(w2, w2);
    float2 w5 = cmul(w3, w2);
    float2 w6 = cmul(w3, w3);
    float2 w7 = cmul(w4, w3);
    v[1] = cmul(v[1], w1); v[2] = cmul(v[2], w2); v[3] = cmul(v[3], w3);
    v[4] = cmul(v[4], w4); v[5] = cmul(v[5], w5); v[6] = cmul(v[6], w6);
    v[7] = cmul(v[7], w7);
}

__device__ __forceinline__ void twiddle_in_conj(float2 v[8], float2 w1) {
    float2 w2 = cmul(w1, w1);
    float2 w3 = cmul(w2, w1);
    float2 w4 = cmul(w2, w2);
    float2 w5 = cmul(w3, w2);
    float2 w6 = cmul(w3, w3);
    float2 w7 = cmul(w4, w3);
    v[1] = cmulc(v[1], w1); v[2] = cmulc(v[2], w2); v[3] = cmulc(v[3], w3);
    v[4] = cmulc(v[4], w4); v[5] = cmulc(v[5], w5); v[6] = cmulc(v[6], w6);
    v[7] = cmulc(v[7], w7);
}

// ---------------------------------------------------------------------------
// Weight table in base-8 digit-reversed layout (both dims).
// ---------------------------------------------------------------------------
__device__ __forceinline__ int octrev9(int p) {
    return ((p & 7) << 6) | (p & 56) | ((p >> 6) & 7);
}

__global__ void k_weights(const float* __restrict__ param) {
    int idx = blockIdx.x * blockDim.x + threadIdx.x;
    if (idx >= 3 * PLANE) return;
    int c   = idx >> 18;
    int rem = idx & (PLANE - 1);
    int k1  = octrev9(rem >> 9);
    int k2  = octrev9(rem & (N - 1));
    int sh  = (k1 + HALF) & (N - 1);
    int sw  = (k2 + HALF) & (N - 1);

    float dh = fabsf((float)(sh - HALF));
    float dw = fabsf((float)(sw - HALF));
    float r2 = dh * dh + dw * dw;
    float mval;
    if (r2 <= 1.0f) {
        mval = 0.5f;                               // SMOOTHNESS
    } else {
        float dist = sqrtf(r2) * (1.0f / 256.0f);
        mval = fmaxf(1.0f, dist * 2.0f);           // dist / SMOOTHNESS
    }
    float pv = param[c * PLANE + sh * N + sw];
    g_wbr[idx] = mval * pv * (1.0f / (float)PLANE);
}

// ---------------------------------------------------------------------------
// Row forward FFT (radix-8 DIF) on packed planes z = a + i*b.
// 4 rows/block (256 threads). Output digit-reversed as half2, 2x uint4/thread.
// Packed plane pi -> real plane 6*(pi/3) + (pi%3), imag plane = real + 3.
// ---------------------------------------------------------------------------
__global__ void __launch_bounds__(256) k_row_fwd(const float* __restrict__ x) {
    __shared__ float2 LUT[N];
    __shared__ float2 S[4 * 576];

    int tid = threadIdx.x;
    {
        float s, c;
        sincospif(-(float)tid * (1.0f / 256.0f), &s, &c);
        LUT[tid] = make_float2(c, s);
        sincospif(-(float)(tid + 256) * (1.0f / 256.0f), &s, &c);
        LUT[tid + 256] = make_float2(c, s);
    }
    int rl = tid >> 6;
    int t  = tid & 63;
    float2* Sr = S + rl * 576;

    int prow = blockIdx.x * 4 + rl;
    int pi   = prow >> 9;
    int r    = prow & (N - 1);
    int bp   = pi / 3;
    int ch   = pi - 3 * bp;
    const float* xre = x + (size_t)(6 * bp + ch) * PLANE + (size_t)r * N;
    const float* xim = xre + (size_t)3 * PLANE;

    float2 v[8];
    #pragma unroll
    for (int q = 0; q < 8; ++q) {
        int p = t + (q << 6);
        v[q] = make_float2(xre[p], xim[p]);
    }
    __syncthreads();   // LUT ready

    // stage m=64 (j = t)
    dft8<false>(v);
    twiddle_out(v, LUT[t]);
    #pragma unroll
    for (int r8 = 0; r8 < 8; ++r8) { int p = t + (r8 << 6); Sr[SMAP(p)] = v[r8]; }
    __syncthreads();
    #pragma unroll
    for (int q = 0; q < 8; ++q) { int p = ((t >> 3) << 6) + (t & 7) + (q << 3); v[q] = Sr[SMAP(p)]; }
    __syncthreads();

    // stage m=8 (j = t&7)
    dft8<false>(v);
    twiddle_out(v, LUT[(t & 7) << 3]);
    #pragma unroll
    for (int r8 = 0; r8 < 8; ++r8) { int p = ((t >> 3) << 6) + (t & 7) + (r8 << 3); Sr[SMAP(p)] = v[r8]; }
    __syncthreads();
    #pragma unroll
    for (int q = 0; q < 8; ++q) { int p = (t << 3) + q; v[q] = Sr[SMAP(p)]; }

    // stage m=1
    dft8<false>(v);

    uint4* o = (uint4*)(g_spec + (size_t)prow * N + (t << 3));
    o[0] = make_uint4(pack_h2(v[0]), pack_h2(v[1]), pack_h2(v[2]), pack_h2(v[3]));
    o[1] = make_uint4(pack_h2(v[4]), pack_h2(v[5]), pack_h2(v[6]), pack_h2(v[7]));
}

// ---------------------------------------------------------------------------
// Fused column pass: fwd radix-8 DIF -> real weight multiply -> inv radix-8 DIT.
// Block = 8 columns of one packed plane; c = tid&7, u = tid>>3.
// ---------------------------------------------------------------------------
__global__ void __launch_bounds__(512) k_col_fused() {
    __shared__ float2 LUT[N];
    __shared__ float2 S[575 * 8];

    int tid  = threadIdx.x;
    {
        float s, c;
        sincospif(-(float)tid * (1.0f / 256.0f), &s, &c);
        if (tid < HALF * 2) LUT[tid] = make_float2(c, s);
    }
    int c    = tid & 7;
    int u    = tid >> 3;
    int img  = blockIdx.x >> 6;          // 0..47
    int col0 = (blockIdx.x & 63) << 3;
    int ch   = img % 3;

    unsigned* base = g_spec + (size_t)img * PLANE + col0 + c;
    int h64 = (u >> 3) << 6;
    int j8  = u & 7;

    float2 v[8];
    #pragma unroll
    for (int q = 0; q < 8; ++q) v[q] = unpack_h2(base[(size_t)(u + (q << 6)) * N]);
    __syncthreads();   // LUT ready

    // ---- forward: stage m=64 ----
    dft8<false>(v);
    twiddle_out(v, LUT[u]);
    #pragma unroll
    for (int r = 0; r < 8; ++r) { int p = u + (r << 6); S[(SMAP(p) << 3) | c] = v[r]; }
    __syncthreads();
    #pragma unroll
    for (int q = 0; q < 8; ++q) { int p = h64 + j8 + (q << 3); v[q] = S[(SMAP(p) << 3) | c]; }
    __syncthreads();

    // ---- forward: stage m=8 ----
    dft8<false>(v);
    twiddle_out(v, LUT[j8 << 3]);
    #pragma unroll
    for (int r = 0; r < 8; ++r) { int p = h64 + j8 + (r << 3); S[(SMAP(p) << 3) | c] = v[r]; }
    __syncthreads();
    #pragma unroll
    for (int q = 0; q < 8; ++q) { int p = (u << 3) + q; v[q] = S[(SMAP(p) << 3) | c]; }

    // ---- forward: stage m=1 ----
    dft8<false>(v);

    // ---- weight multiply (real W; digit-reversed in both dims) ----
    const float* wp = g_wbr + (size_t)ch * PLANE + (size_t)(u << 3) * N + col0 + c;
    #pragma unroll
    for (int r = 0; r < 8; ++r) {
        float w = wp[(size_t)r * N];
        v[r].x *= w; v[r].y *= w;
    }

    // ---- inverse: stage m=1 (registers already hold positions 8u+q) ----
    dft8<true>(v);
    __syncthreads();
    #pragma unroll
    for (int r = 0; r < 8; ++r) { int p = (u << 3) + r; S[(SMAP(p) << 3) | c] = v[r]; }
    __syncthreads();
    #pragma unroll
    for (int q = 0; q < 8; ++q) { int p = h64 + j8 + (q << 3); v[q] = S[(SMAP(p) << 3) | c]; }
    __syncthreads();

    // ---- inverse: stage m=8 ----
    twiddle_in_conj(v, LUT[j8 << 3]);
    dft8<true>(v);
    #pragma unroll
    for (int r = 0; r < 8; ++r) { int p = h64 + j8 + (r << 3); S[(SMAP(p) << 3) | c] = v[r]; }
    __syncthreads();
    #pragma unroll
    for (int q = 0; q < 8; ++q) { int p = u + (q << 6); v[q] = S[(SMAP(p) << 3) | c]; }

    // ---- inverse: stage m=64 ----
    twiddle_in_conj(v, LUT[u]);
    dft8<true>(v);
    #pragma unroll
    for (int r = 0; r < 8; ++r) base[(size_t)(u + (r << 6)) * N] = pack_h2(v[r]);
}

// ---------------------------------------------------------------------------
// Row inverse FFT (radix-8 DIT, digit-reversed half2 input -> natural).
// 4 rows/block (256 threads). out_a = Re, out_b = Im, coalesced real stores.
// ---------------------------------------------------------------------------
__global__ void __launch_bounds__(256) k_row_inv(float* __restrict__ out) {
    __shared__ float2 LUT[N];
    __shared__ float2 S[4 * 576];

    int tid = threadIdx.x;
    {
        float s, c;
        sincospif(-(float)tid * (1.0f / 256.0f), &s, &c);
        LUT[tid] = make_float2(c, s);
        sincospif(-(float)(tid + 256) * (1.0f / 256.0f), &s, &c);
        LUT[tid + 256] = make_float2(c, s);
    }
    int rl = tid >> 6;
    int t  = tid & 63;
    float2* Sr = S + rl * 576;

    int prow = blockIdx.x * 4 + rl;
    int pi   = prow >> 9;
    int r    = prow & (N - 1);
    int bp   = pi / 3;
    int ch   = pi - 3 * bp;
    int h64  = (t >> 3) << 6;
    int j8   = t & 7;

    const uint4* in4 = (const uint4*)(g_spec + (size_t)prow * N + (t << 3));
    float2 v[8];
    {
        uint4 a0 = in4[0], a1 = in4[1];
        v[0] = unpack_h2(a0.x); v[1] = unpack_h2(a0.y);
        v[2] = unpack_h2(a0.z); v[3] = unpack_h2(a0.w);
        v[4] = unpack_h2(a1.x); v[5] = unpack_h2(a1.y);
        v[6] = unpack_h2(a1.z); v[7] = unpack_h2(a1.w);
    }

    // stage m=1
    dft8<true>(v);
    #pragma unroll
    for (int r8 = 0; r8 < 8; ++r8) { int p = (t << 3) + r8; Sr[SMAP(p)] = v[r8]; }
    __syncthreads();   // also covers LUT init
    #pragma unroll
    for (int q = 0; q < 8; ++q) { int p = h64 + j8 + (q << 3); v[q] = Sr[SMAP(p)]; }
    __syncthreads();

    // stage m=8
    twiddle_in_conj(v, LUT[j8 << 3]);
    dft8<true>(v);
    #pragma unroll
    for (int r8 = 0; r8 < 8; ++r8) { int p = h64 + j8 + (r8 << 3); Sr[SMAP(p)] = v[r8]; }
    __syncthreads();
    #pragma unroll
    for (int q = 0; q < 8; ++q) { int p = t + (q << 6); v[q] = Sr[SMAP(p)]; }

    // stage m=64
    twiddle_in_conj(v, LUT[t]);
    dft8<true>(v);

    float* ore = out + (size_t)(6 * bp + ch) * PLANE + (size_t)r * N;
    float* oim = ore + (size_t)3 * PLANE;
    #pragma unroll
    for (int r8 = 0; r8 < 8; ++r8) {
        int p = t + (r8 << 6);
        ore[p] = v[r8].x;
        oim[p] = v[r8].y;
    }
}

// ---------------------------------------------------------------------------
extern "C" void kernel_launch(void* const* d_in, const int* in_sizes, int n_in,
                              void* d_out, int out_size) {
    const float* x = (const float*)d_in[0];
    const float* p = (const float*)d_in[1];
    if (n_in >= 2 && in_sizes[0] < in_sizes[1]) { const float* t = x; x = p; p = t; }
    float* out = (float*)d_out;

    k_weights<<<(3 * PLANE + 255) / 256, 256>>>(p);
    k_row_fwd<<<NPK * N / 4, 256>>>(x);
    k_col_fused<<<NPK * (N / 8), 512>>>();
    k_row_inv<<<NPK * N / 4, 256>>>(out);
}

// round 10
// speedup vs baseline: 5.9478x; 1.0192x over previous
#include <cuda_runtime.h>
#include <cuda_fp16.h>
#include <math.h>

// ---------------------------------------------------------------------------
// FourierTransformLayer: out = real(ifft2( fft2(x) * W )),
//   W[c,k1,k2] = mask((k1+256)&511,(k2+256)&511) * param[c,...] / 512^2
//
// Real-input packing: two same-channel images a,b packed z = a + i*b (W real
// and conjugate-symmetric -> out_a = Re, out_b = Im). 48 complex planes.
// Register-resident radix-8 FFTs (512 = 8^3): 64 threads/FFT, 8 complex per
// thread, 2 smem exchanges. Forward DIF leaves base-8 digit-reversed order,
// weights baked in that layout, inverse DIT consumes it.
// Intermediate spectrum stored as half2 (fp32 math, quantize at scratch hops).
//
// R10: packed f32x2 add/sub for complex butterflies (PTX-only on sm_103a),
// sequential twiddle power chains (2 live regs), launch_bounds occupancy caps.
// ---------------------------------------------------------------------------

#define N      512
#define HALF   256
#define NPK    48            // packed planes (96 real planes / 2)
#define PLANE  (N * N)
#define SMAP(p) ((p) + ((p) >> 3))   // bank-conflict skew

__device__ unsigned g_spec[(size_t)NPK * PLANE];  // half2 per element, 48 MB
__device__ float    g_wbr[3 * PLANE];             // weights, digit-reversed layout

__device__ __forceinline__ unsigned pack_h2(float2 a) {
    __half2 h = __floats2half2_rn(a.x, a.y);
    return *reinterpret_cast<unsigned*>(&h);
}
__device__ __forceinline__ float2 unpack_h2(unsigned u) {
    __half2 h = *reinterpret_cast<__half2*>(&u);
    return __half22float2(h);
}

// ---- packed f32x2 complex add/sub/scale (ptxas never emits these from C++) ----
__device__ __forceinline__ float2 cadd(float2 a, float2 b) {
    float2 r;
    asm("{\n\t.reg .b64 ra, rb, rr;\n\t"
        "mov.b64 ra, {%2, %3};\n\t"
        "mov.b64 rb, {%4, %5};\n\t"
        "add.rn.f32x2 rr, ra, rb;\n\t"
        "mov.b64 {%0, %1}, rr;\n\t}"
        : "=f"(r.x), "=f"(r.y)
        : "f"(a.x), "f"(a.y), "f"(b.x), "f"(b.y));
    return r;
}
__device__ __forceinline__ float2 csub(float2 a, float2 b) {
    float2 r;
    asm("{\n\t.reg .b64 ra, rb, rr;\n\t"
        "mov.b64 ra, {%2, %3};\n\t"
        "mov.b64 rb, {%4, %5};\n\t"
        "sub.rn.f32x2 rr, ra, rb;\n\t"
        "mov.b64 {%0, %1}, rr;\n\t}"
        : "=f"(r.x), "=f"(r.y)
        : "f"(a.x), "f"(a.y), "f"(b.x), "f"(b.y));
    return r;
}
__device__ __forceinline__ float2 cscale(float2 a, float w) {
    float2 r;
    asm("{\n\t.reg .b64 ra, rb, rr;\n\t"
        "mov.b64 ra, {%2, %3};\n\t"
        "mov.b64 rb, {%4, %4};\n\t"
        "mul.rn.f32x2 rr, ra, rb;\n\t"
        "mov.b64 {%0, %1}, rr;\n\t}"
        : "=f"(r.x), "=f"(r.y)
        : "f"(a.x), "f"(a.y), "f"(w));
    return r;
}

__device__ __forceinline__ float2 cmul(float2 a, float2 b) {
    return make_float2(a.x * b.x - a.y * b.y, a.x * b.y + a.y * b.x);
}
// a * conj(b)
__device__ __forceinline__ float2 cmulc(float2 a, float2 b) {
    return make_float2(a.x * b.x + a.y * b.y, a.y * b.x - a.x * b.y);
}

// 8-point DFT, natural order in AND out. INV -> conjugate twiddles (unnormalized).
template<bool INV>
__device__ __forceinline__ void dft8(float2 v[8]) {
    const float s = 0.70710678118654752440f;
    float2 b0 = cadd(v[0], v[4]), t4 = csub(v[0], v[4]);
    float2 b1 = cadd(v[1], v[5]), t5 = csub(v[1], v[5]);
    float2 b2 = cadd(v[2], v[6]), t6 = csub(v[2], v[6]);
    float2 b3 = cadd(v[3], v[7]), t7 = csub(v[3], v[7]);
    float2 b4 = t4;
    float2 b5 = INV ? make_float2(s * (t5.x - t5.y), s * (t5.x + t5.y))
                    : make_float2(s * (t5.x + t5.y), s * (t5.y - t5.x));
    float2 b6 = INV ? make_float2(-t6.y, t6.x)
                    : make_float2(t6.y, -t6.x);
    float2 b7 = INV ? make_float2(-s * (t7.x + t7.y), s * (t7.x - t7.y))
                    : make_float2(s * (t7.y - t7.x), -s * (t7.x + t7.y));
    float2 c0 = cadd(b0, b2), u2 = csub(b0, b2);
    float2 c1 = cadd(b1, b3), u3 = csub(b1, b3);
    float2 c4 = cadd(b4, b6), u6 = csub(b4, b6);
    float2 c5 = cadd(b5, b7), u7 = csub(b5, b7);
    float2 c2 = u2;
    float2 c3 = INV ? make_float2(-u3.y, u3.x) : make_float2(u3.y, -u3.x);
    float2 c6 = u6;
    float2 c7 = INV ? make_float2(-u7.y, u7.x) : make_float2(u7.y, -u7.x);
    v[0] = cadd(c0, c1); v[4] = csub(c0, c1);
    v[2] = cadd(c2, c3); v[6] = csub(c2, c3);
    v[1] = cadd(c4, c5); v[5] = csub(c4, c5);
    v[3] = cadd(c6, c7); v[7] = csub(c6, c7);
}

// Sequential power chain: v[r] *= w1^r  (2 live twiddle registers)
__device__ __forceinline__ void twiddle_out(float2 v[8], float2 w1) {
    float2 w = w1;
    v[1] = cmul(v[1], w);
    #pragma unroll
    for (int r = 2; r < 8; ++r) {
        w = cmul(w, w1);
        v[r] = cmul(v[r], w);
    }
}

// v[q] *= conj(w1^q)
__device__ __forceinline__ void twiddle_in_conj(float2 v[8], float2 w1) {
    float2 w = w1;
    v[1] = cmulc(v[1], w);
    #pragma unroll
    for (int r = 2; r < 8; ++r) {
        w = cmul(w, w1);
        v[r] = cmulc(v[r], w);
    }
}

// ---------------------------------------------------------------------------
// Weight table in base-8 digit-reversed layout (both dims).
// ---------------------------------------------------------------------------
__device__ __forceinline__ int octrev9(int p) {
    return ((p & 7) << 6) | (p & 56) | ((p >> 6) & 7);
}

__global__ void k_weights(const float* __restrict__ param) {
    int idx = blockIdx.x * blockDim.x + threadIdx.x;
    if (idx >= 3 * PLANE) return;
    int c   = idx >> 18;
    int rem = idx & (PLANE - 1);
    int k1  = octrev9(rem >> 9);
    int k2  = octrev9(rem & (N - 1));
    int sh  = (k1 + HALF) & (N - 1);
    int sw  = (k2 + HALF) & (N - 1);

    float dh = fabsf((float)(sh - HALF));
    float dw = fabsf((float)(sw - HALF));
    float r2 = dh * dh + dw * dw;
    float mval;
    if (r2 <= 1.0f) {
        mval = 0.5f;                               // SMOOTHNESS
    } else {
        float dist = sqrtf(r2) * (1.0f / 256.0f);
        mval = fmaxf(1.0f, dist * 2.0f);           // dist / SMOOTHNESS
    }
    float pv = param[c * PLANE + sh * N + sw];
    g_wbr[idx] = mval * pv * (1.0f / (float)PLANE);
}

// ---------------------------------------------------------------------------
// Row forward FFT (radix-8 DIF) on packed planes z = a + i*b.
// 4 rows/block (256 threads). Output digit-reversed as half2, 2x uint4/thread.
// ---------------------------------------------------------------------------
__global__ void __launch_bounds__(256, 6) k_row_fwd(const float* __restrict__ x) {
    __shared__ float2 LUT[N];
    __shared__ float2 S[4 * 576];

    int tid = threadIdx.x;
    {
        float s, c;
        sincospif(-(float)tid * (1.0f / 256.0f), &s, &c);
        LUT[tid] = make_float2(c, s);
        sincospif(-(float)(tid + 256) * (1.0f / 256.0f), &s, &c);
        LUT[tid + 256] = make_float2(c, s);
    }
    int rl = tid >> 6;
    int t  = tid & 63;
    float2* Sr = S + rl * 576;

    int prow = blockIdx.x * 4 + rl;
    int pi   = prow >> 9;
    int r    = prow & (N - 1);
    int bp   = pi / 3;
    int ch   = pi - 3 * bp;
    const float* xre = x + (size_t)(6 * bp + ch) * PLANE + (size_t)r * N;
    const float* xim = xre + (size_t)3 * PLANE;

    float2 v[8];
    #pragma unroll
    for (int q = 0; q < 8; ++q) {
        int p = t + (q << 6);
        v[q] = make_float2(xre[p], xim[p]);
    }
    __syncthreads();   // LUT ready

    // stage m=64 (j = t)
    dft8<false>(v);
    twiddle_out(v, LUT[t]);
    #pragma unroll
    for (int r8 = 0; r8 < 8; ++r8) { int p = t + (r8 << 6); Sr[SMAP(p)] = v[r8]; }
    __syncthreads();
    #pragma unroll
    for (int q = 0; q < 8; ++q) { int p = ((t >> 3) << 6) + (t & 7) + (q << 3); v[q] = Sr[SMAP(p)]; }
    __syncthreads();

    // stage m=8 (j = t&7)
    dft8<false>(v);
    twiddle_out(v, LUT[(t & 7) << 3]);
    #pragma unroll
    for (int r8 = 0; r8 < 8; ++r8) { int p = ((t >> 3) << 6) + (t & 7) + (r8 << 3); Sr[SMAP(p)] = v[r8]; }
    __syncthreads();
    #pragma unroll
    for (int q = 0; q < 8; ++q) { int p = (t << 3) + q; v[q] = Sr[SMAP(p)]; }

    // stage m=1
    dft8<false>(v);

    uint4* o = (uint4*)(g_spec + (size_t)prow * N + (t << 3));
    o[0] = make_uint4(pack_h2(v[0]), pack_h2(v[1]), pack_h2(v[2]), pack_h2(v[3]));
    o[1] = make_uint4(pack_h2(v[4]), pack_h2(v[5]), pack_h2(v[6]), pack_h2(v[7]));
}

// ---------------------------------------------------------------------------
// Fused column pass: fwd radix-8 DIF -> real weight multiply -> inv radix-8 DIT.
// Block = 8 columns of one packed plane; c = tid&7, u = tid>>3.
// ---------------------------------------------------------------------------
__global__ void __launch_bounds__(512, 3) k_col_fused() {
    __shared__ float2 LUT[N];
    __shared__ float2 S[575 * 8];

    int tid  = threadIdx.x;
    {
        float s, c;
        sincospif(-(float)tid * (1.0f / 256.0f), &s, &c);
        LUT[tid] = make_float2(c, s);
    }
    int c    = tid & 7;
    int u    = tid >> 3;
    int img  = blockIdx.x >> 6;          // 0..47
    int col0 = (blockIdx.x & 63) << 3;
    int ch   = img % 3;

    unsigned* base = g_spec + (size_t)img * PLANE + col0 + c;
    int h64 = (u >> 3) << 6;
    int j8  = u & 7;

    float2 v[8];
    #pragma unroll
    for (int q = 0; q < 8; ++q) v[q] = unpack_h2(base[(size_t)(u + (q << 6)) * N]);
    __syncthreads();   // LUT ready

    // ---- forward: stage m=64 ----
    dft8<false>(v);
    twiddle_out(v, LUT[u]);
    #pragma unroll
    for (int r = 0; r < 8; ++r) { int p = u + (r << 6); S[(SMAP(p) << 3) | c] = v[r]; }
    __syncthreads();
    #pragma unroll
    for (int q = 0; q < 8; ++q) { int p = h64 + j8 + (q << 3); v[q] = S[(SMAP(p) << 3) | c]; }
    __syncthreads();

    // ---- forward: stage m=8 ----
    dft8<false>(v);
    twiddle_out(v, LUT[j8 << 3]);
    #pragma unroll
    for (int r = 0; r < 8; ++r) { int p = h64 + j8 + (r << 3); S[(SMAP(p) << 3) | c] = v[r]; }
    __syncthreads();
    #pragma unroll
    for (int q = 0; q < 8; ++q) { int p = (u << 3) + q; v[q] = S[(SMAP(p) << 3) | c]; }

    // ---- forward: stage m=1 ----
    dft8<false>(v);

    // ---- weight multiply (real W; digit-reversed in both dims) ----
    const float* wp = g_wbr + (size_t)ch * PLANE + (size_t)(u << 3) * N + col0 + c;
    #pragma unroll
    for (int r = 0; r < 8; ++r) v[r] = cscale(v[r], wp[(size_t)r * N]);

    // ---- inverse: stage m=1 (registers already hold positions 8u+q) ----
    dft8<true>(v);
    __syncthreads();
    #pragma unroll
    for (int r = 0; r < 8; ++r) { int p = (u << 3) + r; S[(SMAP(p) << 3) | c] = v[r]; }
    __syncthreads();
    #pragma unroll
    for (int q = 0; q < 8; ++q) { int p = h64 + j8 + (q << 3); v[q] = S[(SMAP(p) << 3) | c]; }
    __syncthreads();

    // ---- inverse: stage m=8 ----
    twiddle_in_conj(v, LUT[j8 << 3]);
    dft8<true>(v);
    #pragma unroll
    for (int r = 0; r < 8; ++r) { int p = h64 + j8 + (r << 3); S[(SMAP(p) << 3) | c] = v[r]; }
    __syncthreads();
    #pragma unroll
    for (int q = 0; q < 8; ++q) { int p = u + (q << 6); v[q] = S[(SMAP(p) << 3) | c]; }

    // ---- inverse: stage m=64 ----
    twiddle_in_conj(v, LUT[u]);
    dft8<true>(v);
    #pragma unroll
    for (int r = 0; r < 8; ++r) base[(size_t)(u + (r << 6)) * N] = pack_h2(v[r]);
}

// ---------------------------------------------------------------------------
// Row inverse FFT (radix-8 DIT, digit-reversed half2 input -> natural).
// 4 rows/block (256 threads). out_a = Re, out_b = Im, coalesced real stores.
// ---------------------------------------------------------------------------
__global__ void __launch_bounds__(256, 6) k_row_inv(float* __restrict__ out) {
    __shared__ float2 LUT[N];
    __shared__ float2 S[4 * 576];

    int tid = threadIdx.x;
    {
        float s, c;
        sincospif(-(float)tid * (1.0f / 256.0f), &s, &c);
        LUT[tid] = make_float2(c, s);
        sincospif(-(float)(tid + 256) * (1.0f / 256.0f), &s, &c);
        LUT[tid + 256] = make_float2(c, s);
    }
    int rl = tid >> 6;
    int t  = tid & 63;
    float2* Sr = S + rl * 576;

    int prow = blockIdx.x * 4 + rl;
    int pi   = prow >> 9;
    int r    = prow & (N - 1);
    int bp   = pi / 3;
    int ch   = pi - 3 * bp;
    int h64  = (t >> 3) << 6;
    int j8   = t & 7;

    const uint4* in4 = (const uint4*)(g_spec + (size_t)prow * N + (t << 3));
    float2 v[8];
    {
        uint4 a0 = in4[0], a1 = in4[1];
        v[0] = unpack_h2(a0.x); v[1] = unpack_h2(a0.y);
        v[2] = unpack_h2(a0.z); v[3] = unpack_h2(a0.w);
        v[4] = unpack_h2(a1.x); v[5] = unpack_h2(a1.y);
        v[6] = unpack_h2(a1.z); v[7] = unpack_h2(a1.w);
    }

    // stage m=1
    dft8<true>(v);
    #pragma unroll
    for (int r8 = 0; r8 < 8; ++r8) { int p = (t << 3) + r8; Sr[SMAP(p)] = v[r8]; }
    __syncthreads();   // also covers LUT init
    #pragma unroll
    for (int q = 0; q < 8; ++q) { int p = h64 + j8 + (q << 3); v[q] = Sr[SMAP(p)]; }
    __syncthreads();

    // stage m=8
    twiddle_in_conj(v, LUT[j8 << 3]);
    dft8<true>(v);
    #pragma unroll
    for (int r8 = 0; r8 < 8; ++r8) { int p = h64 + j8 + (r8 << 3); Sr[SMAP(p)] = v[r8]; }
    __syncthreads();
    #pragma unroll
    for (int q = 0; q < 8; ++q) { int p = t + (q << 6); v[q] = Sr[SMAP(p)]; }

    // stage m=64
    twiddle_in_conj(v, LUT[t]);
    dft8<true>(v);

    float* ore = out + (size_t)(6 * bp + ch) * PLANE + (size_t)r * N;
    float* oim = ore + (size_t)3 * PLANE;
    #pragma unroll
    for (int r8 = 0; r8 < 8; ++r8) {
        int p = t + (r8 << 6);
        ore[p] = v[r8].x;
        oim[p] = v[r8].y;
    }
}

// ---------------------------------------------------------------------------
extern "C" void kernel_launch(void* const* d_in, const int* in_sizes, int n_in,
                              void* d_out, int out_size) {
    const float* x = (const float*)d_in[0];
    const float* p = (const float*)d_in[1];
    if (n_in >= 2 && in_sizes[0] < in_sizes[1]) { const float* t = x; x = p; p = t; }
    float* out = (float*)d_out;

    k_weights<<<(3 * PLANE + 255) / 256, 256>>>(p);
    k_row_fwd<<<NPK * N / 4, 256>>>(x);
    k_col_fused<<<NPK * (N / 8), 512>>>();
    k_row_inv<<<NPK * N / 4, 256>>>(out);
}